// round 8
// baseline (speedup 1.0000x reference)
#include <cuda_runtime.h>
#include <cstdint>

typedef unsigned long long ull;

// Problem constants (fixed by the reference).
#define NP    16384
#define FIN   64
#define MC    4096
#define KN    64
#define FH    64
#define FO    128
#define FD    67
#define FPAD  68
#define R2F   0.04f

// Scratch (static __device__ — no allocations allowed).
__device__ int   g_idx[MC];
__device__ float g_pos_s[MC * 3];
__device__ int   g_nbr[MC * KN];
__device__ int   g_cnt[MC];
// Morton-reordered cloud
__device__ __align__(128) float g_px[NP];
__device__ __align__(128) float g_py[NP];
__device__ __align__(128) float g_pz[NP];
__device__ __align__(128) int   g_orig[NP];

// ---------------------------------------------------------------------------
// 0) Build: Morton sort (bitonic, one CTA) -> reordered coords.
// ---------------------------------------------------------------------------
__device__ __forceinline__ unsigned expand10(unsigned v) {
    v &= 1023u;
    v = (v | (v << 16)) & 0x030000FFu;
    v = (v | (v << 8))  & 0x0300F00Fu;
    v = (v | (v << 4))  & 0x030C30C3u;
    v = (v | (v << 2))  & 0x09249249u;
    return v;
}

#define BLD_T 512
#define BLD_SMEM (NP * 8)

__global__ __launch_bounds__(BLD_T) void build_kernel(const float* __restrict__ pos)
{
    extern __shared__ ull sk[];
    int t = threadIdx.x;

    for (int i = t; i < NP; i += BLD_T) {
        float x = pos[3 * i + 0], y = pos[3 * i + 1], z = pos[3 * i + 2];
        unsigned ux = (unsigned)fminf(1023.f, fmaxf(0.f, (x + 5.12f) * 100.0f));
        unsigned uy = (unsigned)fminf(1023.f, fmaxf(0.f, (y + 5.12f) * 100.0f));
        unsigned uz = (unsigned)fminf(1023.f, fmaxf(0.f, (z + 5.12f) * 100.0f));
        unsigned code = (expand10(ux) << 2) | (expand10(uy) << 1) | expand10(uz);
        sk[i] = ((ull)code << 32) | (unsigned)i;
    }
    __syncthreads();

    for (unsigned k2 = 2; k2 <= NP; k2 <<= 1) {
        for (unsigned j = k2 >> 1; j > 0; j >>= 1) {
            for (unsigned i = t; i < NP; i += BLD_T) {
                unsigned ixj = i ^ j;
                if (ixj > i) {
                    ull a = sk[i], b = sk[ixj];
                    bool up = ((i & k2) == 0);
                    if ((a > b) == up) { sk[i] = b; sk[ixj] = a; }
                }
            }
            __syncthreads();
        }
    }

    for (int i = t; i < NP; i += BLD_T) {
        unsigned idx = (unsigned)sk[i];
        g_px[i] = pos[3 * idx + 0];
        g_py[i] = pos[3 * idx + 1];
        g_pz[i] = pos[3 * idx + 2];
        g_orig[i] = (int)idx;
    }
}

// ---------------------------------------------------------------------------
// 1) FPS — single persistent CTA, 512 threads. Thread t owns points
//    [32t, 32t+32) as TWO 16-pt Morton groups. md[32] lives in REGISTERS
//    with fully static indexing; group center/radius/trigger in scalar regs.
//    Dirty groups are updated SIMT-parallel (adjacent dirty groups =
//    adjacent lanes = one masked pass). Selection: 2 REDUX + 3 barriers.
//    Skipped groups are provably unchanged -> bit-identical to dense FPS.
// ---------------------------------------------------------------------------
#define FPS_T 512
#define SPLIT 128
#define FPS_SMEM (NP * 8 + NP * 4 + 256)

__global__ __launch_bounds__(FPS_T) void fps_kernel(const float* __restrict__ pos)
{
    extern __shared__ unsigned char raw[];
    float2*   s_xy  = (float2*)raw;                       // [NP]
    float*    s_z   = (float*)(raw + NP * 8);             // [NP]
    unsigned* s_wm  = (unsigned*)(raw + NP * 12);         // [16]
    unsigned* s_win = s_wm + 16;                          // [2]
    float*    s_q   = (float*)(s_win + 2);                // [3]

    const int t = threadIdx.x, lane = t & 31, w = t >> 5;
    const int base = t * 32;
    const float INF = __int_as_float(0x7f800000);

    float md[32];
    float x0lo = 1e30f, x0hi = -1e30f, y0lo = 1e30f, y0hi = -1e30f, z0lo = 1e30f, z0hi = -1e30f;
    float x1lo = 1e30f, x1hi = -1e30f, y1lo = 1e30f, y1hi = -1e30f, z1lo = 1e30f, z1hi = -1e30f;
#pragma unroll
    for (int m = 0; m < 32; m++) {
        int p = base + m;
        float x = g_px[p], y = g_py[p], z = g_pz[p];
        s_xy[p] = make_float2(x, y);
        s_z[p] = z;
        md[m] = INF;
        if (m < 16) {
            x0lo = fminf(x0lo, x); x0hi = fmaxf(x0hi, x);
            y0lo = fminf(y0lo, y); y0hi = fmaxf(y0hi, y);
            z0lo = fminf(z0lo, z); z0hi = fmaxf(z0hi, z);
        } else {
            x1lo = fminf(x1lo, x); x1hi = fmaxf(x1hi, x);
            y1lo = fminf(y1lo, y); y1hi = fmaxf(y1hi, y);
            z1lo = fminf(z1lo, z); z1hi = fmaxf(z1hi, z);
        }
    }
    float c0x = 0.5f * (x0lo + x0hi), c0y = 0.5f * (y0lo + y0hi), c0z = 0.5f * (z0lo + z0hi);
    float c1x = 0.5f * (x1lo + x1hi), c1y = 0.5f * (y1lo + y1hi), c1z = 0.5f * (z1lo + z1hi);
    // Bounding-sphere radius per group (+ conservative margin).
    float r0 = 0.0f, r1 = 0.0f;
#pragma unroll
    for (int m = 0; m < 32; m++) {
        int p = base + m;
        float2 xy = s_xy[p]; float z = s_z[p];
        if (m < 16) {
            float dx = xy.x - c0x, dy = xy.y - c0y, dz = z - c0z;
            r0 = fmaxf(r0, dx * dx + dy * dy + dz * dz);
        } else {
            float dx = xy.x - c1x, dy = xy.y - c1y, dz = z - c1z;
            r1 = fmaxf(r1, dx * dx + dy * dy + dz * dz);
        }
    }
    r0 = __fsqrt_rn(r0) * 1.0005f + 1e-4f;
    r1 = __fsqrt_rn(r1) * 1.0005f + 1e-4f;
    float T0 = INF, T1 = INF, gm0 = INF, gm1 = INF;

    if (t == 0) {
        g_idx[0] = 0;
        s_q[0] = pos[0]; s_q[1] = pos[1]; s_q[2] = pos[2];
        s_win[0] = 0u; s_win[1] = 0u;
    }
    __syncthreads();

    for (int it = 1; it < MC; it++) {
        float qx = s_q[0], qy = s_q[1], qz = s_q[2];

        // ---- Group 0: dirty test + register-resident update ----
        {
            float ddx = qx - c0x, ddy = qy - c0y, ddz = qz - c0z;
            float d2c = ddx * ddx + ddy * ddy + ddz * ddz;
            if (it <= SPLIT || d2c < T0) {
                float gm = -1.0f;
#pragma unroll
                for (int m = 0; m < 16; m++) {
                    int p = base + m;
                    float2 xy = s_xy[p]; float z = s_z[p];
                    float dx = __fadd_rn(xy.x, -qx);
                    float dy = __fadd_rn(xy.y, -qy);
                    float dz = __fadd_rn(z, -qz);
                    float d2 = __fmaf_rn(dz, dz, __fmaf_rn(dy, dy, __fmul_rn(dx, dx)));
                    float mn = fminf(md[m], d2);
                    md[m] = mn;
                    gm = fmaxf(gm, mn);
                }
                gm0 = gm;
                float s = __fsqrt_rn(gm) * 1.0005f + r0;
                T0 = s * s;
            }
        }
        // ---- Group 1 ----
        {
            float ddx = qx - c1x, ddy = qy - c1y, ddz = qz - c1z;
            float d2c = ddx * ddx + ddy * ddy + ddz * ddz;
            if (it <= SPLIT || d2c < T1) {
                float gm = -1.0f;
#pragma unroll
                for (int m = 0; m < 16; m++) {
                    int p = base + 16 + m;
                    float2 xy = s_xy[p]; float z = s_z[p];
                    float dx = __fadd_rn(xy.x, -qx);
                    float dy = __fadd_rn(xy.y, -qy);
                    float dz = __fadd_rn(z, -qz);
                    float d2 = __fmaf_rn(dz, dz, __fmaf_rn(dy, dy, __fmul_rn(dx, dx)));
                    float mn = fminf(md[16 + m], d2);
                    md[16 + m] = mn;
                    gm = fmaxf(gm, mn);
                }
                gm1 = gm;
                float s = __fsqrt_rn(gm) * 1.0005f + r1;
                T1 = s * s;
            }
        }

        // ---- Selection: global max of per-thread maxima ----
        float mymax = fmaxf(gm0, gm1);
        unsigned wm = __reduce_max_sync(0xFFFFFFFFu, __float_as_uint(mymax));
        if (lane == 0) s_wm[w] = wm;
        __syncthreads();                                   // BAR1
        unsigned v = __reduce_max_sync(0xFFFFFFFFu, s_wm[lane & 15]);
        int slot = it & 1;

        // Candidate threads: exact lowest-orig tie rule over their own points.
        unsigned tinv = 0u; float tx = 0.f, ty = 0.f, tz = 0.f;
        if (__float_as_uint(mymax) == v) {
#pragma unroll
            for (int m = 0; m < 32; m++) {
                if (__float_as_uint(md[m]) == v) {
                    unsigned inv = ~(unsigned)g_orig[base + m];
                    if (inv > tinv) {
                        tinv = inv;
                        float2 xy = s_xy[base + m];
                        tx = xy.x; ty = xy.y; tz = s_z[base + m];
                    }
                }
            }
            atomicMax(&s_win[slot], tinv);
        }
        __syncthreads();                                   // BAR2

        unsigned win = s_win[slot];
        if (tinv == win && tinv != 0u) {
            s_q[0] = tx; s_q[1] = ty; s_q[2] = tz;
            g_idx[it] = (int)~win;
        }
        if (t == 0) s_win[slot ^ 1] = 0u;
        __syncthreads();                                   // BAR3
    }
}

// ---------------------------------------------------------------------------
// 2) Gather sampled positions (+ tuple tail if flattened output).
// ---------------------------------------------------------------------------
__global__ void gather_kernel(const float* __restrict__ pos, float* __restrict__ out, int out_size)
{
    int c = blockIdx.x * blockDim.x + threadIdx.x;
    if (c >= MC) return;
    int j = g_idx[c];
    float x = pos[3 * j + 0], y = pos[3 * j + 1], z = pos[3 * j + 2];
    g_pos_s[3 * c + 0] = x; g_pos_s[3 * c + 1] = y; g_pos_s[3 * c + 2] = z;
    int base = MC * FO;
    if (out_size >= base + 3 * MC) {
        out[base + 3 * c + 0] = x; out[base + 3 * c + 1] = y; out[base + 3 * c + 2] = z;
    }
    if (out_size >= base + 4 * MC) out[base + 3 * MC + c] = 0.0f;
}

// ---------------------------------------------------------------------------
// 3) Radius neighbors (unchanged, passing).
// ---------------------------------------------------------------------------
#define RB_C   16
#define RB_T   256
#define RB_CAP 192

__global__ __launch_bounds__(RB_T) void radius_kernel(const float* __restrict__ pos)
{
    __shared__ float scx[RB_C], scy[RB_C], scz[RB_C];
    __shared__ int   scnt[RB_C];
    __shared__ int   sidx[RB_C][RB_CAP];
    __shared__ float sd2[RB_C][RB_CAP];

    int t = threadIdx.x;
    int c0 = blockIdx.x * RB_C;
    if (t < RB_C) {
        scx[t] = g_pos_s[3 * (c0 + t) + 0];
        scy[t] = g_pos_s[3 * (c0 + t) + 1];
        scz[t] = g_pos_s[3 * (c0 + t) + 2];
        scnt[t] = 0;
    }
    __syncthreads();

    for (int j = t; j < NP; j += RB_T) {
        float x = pos[3 * j + 0], y = pos[3 * j + 1], z = pos[3 * j + 2];
#pragma unroll
        for (int c = 0; c < RB_C; c++) {
            float dx = __fadd_rn(scx[c], -x);
            float dy = __fadd_rn(scy[c], -y);
            float dz = __fadd_rn(scz[c], -z);
            float d2 = __fmaf_rn(dz, dz, __fmaf_rn(dy, dy, __fmul_rn(dx, dx)));
            if (d2 <= R2F) {
                int n = atomicAdd(&scnt[c], 1);
                if (n < RB_CAP) { sidx[c][n] = j; sd2[c][n] = d2; }
            }
        }
    }
    __syncthreads();

    for (int c = 0; c < RB_C; c++) {
        int cnt = min(scnt[c], RB_CAP);
        int cg = c0 + c;
        if (cnt <= KN) {
            if (t < cnt) g_nbr[cg * KN + t] = sidx[c][t];
            if (t == 0)  g_cnt[cg] = cnt;
        } else {
            for (int i = t; i < cnt; i += RB_T) {
                float di = sd2[c][i]; int ii = sidx[c][i];
                int rank = 0;
                for (int jj = 0; jj < cnt; jj++) {
                    float dj = sd2[c][jj];
                    rank += (dj < di) || (dj == di && sidx[c][jj] < ii);
                }
                if (rank < KN) g_nbr[cg * KN + rank] = ii;
            }
            if (t == 0) g_cnt[cg] = KN;
        }
    }
}

// ---------------------------------------------------------------------------
// 4) Per-edge MLP + max-pool (unchanged, passing).
// ---------------------------------------------------------------------------
#define ML_T    256
#define ML_GRID 304

#define OFF_W1 0
#define OFF_W2 (OFF_W1 + FD * FH)
#define OFF_W3 (OFF_W2 + FH * FH)
#define OFF_B1 (OFF_W3 + FH * FO)
#define OFF_B2 (OFF_B1 + FH)
#define OFF_B3 (OFF_B2 + FH)
#define OFF_F  (OFF_B3 + FO)
#define OFF_H  (OFF_F + KN * FPAD)
#define OFF_O  (OFF_H + KN * FPAD)
#define ML_SMEM ((OFF_O + FO) * 4)

__global__ __launch_bounds__(ML_T, 2) void mlp_kernel(
    const float* __restrict__ x, const float* __restrict__ pos,
    const float* __restrict__ W1, const float* __restrict__ b1,
    const float* __restrict__ W2, const float* __restrict__ b2,
    const float* __restrict__ W3, const float* __restrict__ b3,
    float* __restrict__ out)
{
    extern __shared__ float sm[];
    float* sW1 = sm + OFF_W1;
    float* sW2 = sm + OFF_W2;
    float* sW3 = sm + OFF_W3;
    float* sb1 = sm + OFF_B1;
    float* sb2 = sm + OFF_B2;
    float* sb3 = sm + OFF_B3;
    float* sF  = sm + OFF_F;
    float* sH  = sm + OFF_H;
    int*   sO  = (int*)(sm + OFF_O);

    int t = threadIdx.x;
    for (int i = t; i < FD * FH; i += ML_T) sW1[i] = W1[i];
    for (int i = t; i < FH * FH; i += ML_T) sW2[i] = W2[i];
    for (int i = t; i < FH * FO; i += ML_T) sW3[i] = W3[i];
    if (t < FH) { sb1[t] = b1[t]; sb2[t] = b2[t]; }
    if (t < FO) sb3[t] = b3[t];

    int ei = t >> 4, ci = t & 15;

    for (int c = blockIdx.x; c < MC; c += gridDim.x) {
        __syncthreads();
        if (t < FO) sO[t] = 0;
        int E = g_cnt[c];
        float cx = g_pos_s[3 * c + 0], cy = g_pos_s[3 * c + 1], cz = g_pos_s[3 * c + 2];

        {
            int e = t >> 2, q = t & 3;
            if (e < E) {
                int nb = g_nbr[c * KN + e];
                const float4* xr = (const float4*)(x + (size_t)nb * FIN);
                float4* dst = (float4*)(sF + e * FPAD + q * 16);
                dst[0] = xr[q * 4 + 0]; dst[1] = xr[q * 4 + 1];
                dst[2] = xr[q * 4 + 2]; dst[3] = xr[q * 4 + 3];
                if (q == 0) {
                    sF[e * FPAD + 64] = pos[3 * nb + 0] - cx;
                    sF[e * FPAD + 65] = pos[3 * nb + 1] - cy;
                    sF[e * FPAD + 66] = pos[3 * nb + 2] - cz;
                    sF[e * FPAD + 67] = 0.0f;
                }
            }
        }
        __syncthreads();
        int ET = (E + 3) >> 2;

        if (ei < ET) {
            float acc[4][4];
#pragma unroll
            for (int j = 0; j < 4; j++)
#pragma unroll
                for (int a = 0; a < 4; a++) acc[j][a] = sb1[ci * 4 + a];
#pragma unroll 4
            for (int k = 0; k < FD; k++) {
                float4 wv = *(const float4*)(sW1 + k * FH + ci * 4);
                float f[4];
#pragma unroll
                for (int j = 0; j < 4; j++) f[j] = sF[(4 * ei + j) * FPAD + k];
#pragma unroll
                for (int j = 0; j < 4; j++) {
                    acc[j][0] += f[j] * wv.x; acc[j][1] += f[j] * wv.y;
                    acc[j][2] += f[j] * wv.z; acc[j][3] += f[j] * wv.w;
                }
            }
#pragma unroll
            for (int j = 0; j < 4; j++)
#pragma unroll
                for (int a = 0; a < 4; a++)
                    sH[(4 * ei + j) * FPAD + ci * 4 + a] = fmaxf(acc[j][a], 0.0f);
        }
        __syncthreads();

        if (ei < ET) {
            float acc[4][4];
#pragma unroll
            for (int j = 0; j < 4; j++)
#pragma unroll
                for (int a = 0; a < 4; a++) acc[j][a] = sb2[ci * 4 + a];
#pragma unroll 4
            for (int k = 0; k < FH; k++) {
                float4 wv = *(const float4*)(sW2 + k * FH + ci * 4);
                float f[4];
#pragma unroll
                for (int j = 0; j < 4; j++) f[j] = sH[(4 * ei + j) * FPAD + k];
#pragma unroll
                for (int j = 0; j < 4; j++) {
                    acc[j][0] += f[j] * wv.x; acc[j][1] += f[j] * wv.y;
                    acc[j][2] += f[j] * wv.z; acc[j][3] += f[j] * wv.w;
                }
            }
#pragma unroll
            for (int j = 0; j < 4; j++)
#pragma unroll
                for (int a = 0; a < 4; a++)
                    sF[(4 * ei + j) * FPAD + ci * 4 + a] = fmaxf(acc[j][a], 0.0f);
        }
        __syncthreads();

        if (ei < ET) {
            float acc[4][8];
#pragma unroll
            for (int j = 0; j < 4; j++)
#pragma unroll
                for (int a = 0; a < 8; a++) acc[j][a] = sb3[ci * 8 + a];
#pragma unroll 4
            for (int k = 0; k < FH; k++) {
                float4 wa = *(const float4*)(sW3 + k * FO + ci * 8);
                float4 wb = *(const float4*)(sW3 + k * FO + ci * 8 + 4);
                float f[4];
#pragma unroll
                for (int j = 0; j < 4; j++) f[j] = sF[(4 * ei + j) * FPAD + k];
#pragma unroll
                for (int j = 0; j < 4; j++) {
                    acc[j][0] += f[j] * wa.x; acc[j][1] += f[j] * wa.y;
                    acc[j][2] += f[j] * wa.z; acc[j][3] += f[j] * wa.w;
                    acc[j][4] += f[j] * wb.x; acc[j][5] += f[j] * wb.y;
                    acc[j][6] += f[j] * wb.z; acc[j][7] += f[j] * wb.w;
                }
            }
#pragma unroll
            for (int a = 0; a < 8; a++) {
                float mv = -1.0f;
#pragma unroll
                for (int j = 0; j < 4; j++)
                    if (4 * ei + j < E) mv = fmaxf(mv, fmaxf(acc[j][a], 0.0f));
                if (mv >= 0.0f) atomicMax(&sO[ci * 8 + a], __float_as_int(mv));
            }
        }
        __syncthreads();
        if (t < FO) out[(size_t)c * FO + t] = __int_as_float(sO[t]);
    }
}

// ---------------------------------------------------------------------------
extern "C" void kernel_launch(void* const* d_in, const int* in_sizes, int n_in,
                              void* d_out, int out_size)
{
    const float* x   = (const float*)d_in[0];
    const float* pos = (const float*)d_in[1];
    const float* W1 = (const float*)d_in[3];
    const float* b1 = (const float*)d_in[4];
    const float* W2 = (const float*)d_in[5];
    const float* b2 = (const float*)d_in[6];
    const float* W3 = (const float*)d_in[7];
    const float* b3 = (const float*)d_in[8];
    float* out = (float*)d_out;

    cudaFuncSetAttribute(build_kernel, cudaFuncAttributeMaxDynamicSharedMemorySize, BLD_SMEM);
    cudaFuncSetAttribute(fps_kernel,   cudaFuncAttributeMaxDynamicSharedMemorySize, FPS_SMEM);
    cudaFuncSetAttribute(mlp_kernel,   cudaFuncAttributeMaxDynamicSharedMemorySize, ML_SMEM);

    build_kernel<<<1, BLD_T, BLD_SMEM>>>(pos);
    fps_kernel<<<1, FPS_T, FPS_SMEM>>>(pos);
    gather_kernel<<<(MC + 255) / 256, 256>>>(pos, out, out_size);
    radius_kernel<<<MC / RB_C, RB_T>>>(pos);
    mlp_kernel<<<ML_GRID, ML_T, ML_SMEM>>>(x, pos, W1, b1, W2, b2, W3, b3, out);
}

// round 9
// speedup vs baseline: 1.3242x; 1.3242x over previous
#include <cuda_runtime.h>
#include <cstdint>

typedef unsigned long long ull;

// Problem constants (fixed by the reference).
#define NP    16384
#define FIN   64
#define MC    4096
#define KN    64
#define FH    64
#define FO    128
#define FD    67
#define FPAD  68
#define R2F   0.04f

// Scratch (static __device__ — no allocations allowed).
__device__ int   g_idx[MC];
__device__ float g_pos_s[MC * 3];
__device__ int   g_nbr[MC * KN];
__device__ int   g_cnt[MC];
// Morton-reordered cloud
__device__ __align__(128) float g_px[NP];
__device__ __align__(128) float g_py[NP];
__device__ __align__(128) float g_pz[NP];
__device__ __align__(128) int   g_orig[NP];

// ---------------------------------------------------------------------------
// 0) Build: Morton sort (bitonic, one CTA) -> reordered coords.
// ---------------------------------------------------------------------------
__device__ __forceinline__ unsigned expand10(unsigned v) {
    v &= 1023u;
    v = (v | (v << 16)) & 0x030000FFu;
    v = (v | (v << 8))  & 0x0300F00Fu;
    v = (v | (v << 4))  & 0x030C30C3u;
    v = (v | (v << 2))  & 0x09249249u;
    return v;
}

#define BLD_T 512
#define BLD_SMEM (NP * 8)

__global__ __launch_bounds__(BLD_T) void build_kernel(const float* __restrict__ pos)
{
    extern __shared__ ull sk[];
    int t = threadIdx.x;

    for (int i = t; i < NP; i += BLD_T) {
        float x = pos[3 * i + 0], y = pos[3 * i + 1], z = pos[3 * i + 2];
        unsigned ux = (unsigned)fminf(1023.f, fmaxf(0.f, (x + 5.12f) * 100.0f));
        unsigned uy = (unsigned)fminf(1023.f, fmaxf(0.f, (y + 5.12f) * 100.0f));
        unsigned uz = (unsigned)fminf(1023.f, fmaxf(0.f, (z + 5.12f) * 100.0f));
        unsigned code = (expand10(ux) << 2) | (expand10(uy) << 1) | expand10(uz);
        sk[i] = ((ull)code << 32) | (unsigned)i;
    }
    __syncthreads();

    for (unsigned k2 = 2; k2 <= NP; k2 <<= 1) {
        for (unsigned j = k2 >> 1; j > 0; j >>= 1) {
            for (unsigned i = t; i < NP; i += BLD_T) {
                unsigned ixj = i ^ j;
                if (ixj > i) {
                    ull a = sk[i], b = sk[ixj];
                    bool up = ((i & k2) == 0);
                    if ((a > b) == up) { sk[i] = b; sk[ixj] = a; }
                }
            }
            __syncthreads();
        }
    }

    for (int i = t; i < NP; i += BLD_T) {
        unsigned idx = (unsigned)sk[i];
        g_px[i] = pos[3 * idx + 0];
        g_py[i] = pos[3 * idx + 1];
        g_pz[i] = pos[3 * idx + 2];
        g_orig[i] = (int)idx;
    }
}

// ---------------------------------------------------------------------------
// 1) FPS — single persistent CTA, 512 threads, R1 skeleton + sphere pruning.
//    Thread t owns the 32 Morton-contiguous points [32t, 32t+32):
//      px/py/md in registers (static indexing ONLY -> no spills),
//      z/orig in smem transposed [m*512+t] (conflict-free LDS).
//    One bounding sphere per thread: skip the update loop when
//    dist^2(q,c) >= (sqrt(lanebest)*1.0005 + r)^2  — every skipped md[m]
//    is provably unchanged => bit-identical to dense FPS.
//    Dirty threads run concurrently (SIMT), worst case == dense R1.
// ---------------------------------------------------------------------------
#define FPS_T 512
#define FPS_SMEM (NP * 4 /*z*/ + NP * 4 /*orig*/ + 256)

__global__ __launch_bounds__(FPS_T) void fps_kernel(const float* __restrict__ pos)
{
    extern __shared__ unsigned char raw[];
    float*    s_z   = (float*)raw;                     // [32][512] transposed
    int*      s_or  = (int*)(raw + NP * 4);            // [32][512] transposed
    unsigned* s_wm  = (unsigned*)(raw + NP * 8);       // [16]
    unsigned* s_win = s_wm + 16;                       // [2]
    float*    s_q   = (float*)(s_win + 2);             // [3]

    const int t = threadIdx.x, lane = t & 31, w = t >> 5;
    const int base = t * 32;
    const float INF = __int_as_float(0x7f800000);

    float px[32], py[32], md[32];
    float cxlo = 1e30f, cxhi = -1e30f, cylo = 1e30f, cyhi = -1e30f,
          czlo = 1e30f, czhi = -1e30f;
#pragma unroll
    for (int m = 0; m < 32; m++) {
        float x = g_px[base + m], y = g_py[base + m], z = g_pz[base + m];
        px[m] = x; py[m] = y;
        s_z[m * FPS_T + t]  = z;
        s_or[m * FPS_T + t] = g_orig[base + m];
        md[m] = INF;
        cxlo = fminf(cxlo, x); cxhi = fmaxf(cxhi, x);
        cylo = fminf(cylo, y); cyhi = fmaxf(cyhi, y);
        czlo = fminf(czlo, z); czhi = fmaxf(czhi, z);
    }
    float cx = 0.5f * (cxlo + cxhi), cy = 0.5f * (cylo + cyhi), cz = 0.5f * (czlo + czhi);
    float r2 = 0.0f;
#pragma unroll
    for (int m = 0; m < 32; m++) {
        float dx = px[m] - cx, dy = py[m] - cy, dz = s_z[m * FPS_T + t] - cz;
        r2 = fmaxf(r2, dx * dx + dy * dy + dz * dz);
    }
    float r = __fsqrt_ru(r2) * 1.0005f + 1e-4f;
    float T = INF, lanebest = INF;

    if (t == 0) {
        g_idx[0] = 0;
        s_q[0] = pos[0]; s_q[1] = pos[1]; s_q[2] = pos[2];
        s_win[0] = 0u; s_win[1] = 0u;
    }
    __syncthreads();

    for (int it = 1; it < MC; it++) {
        float qx = s_q[0], qy = s_q[1], qz = s_q[2];

        // Sphere prune: skip iff q provably can't lower any md in this thread.
        float ddx = qx - cx, ddy = qy - cy, ddz = qz - cz;
        float d2c = ddx * ddx + ddy * ddy + ddz * ddz;
        if (d2c < T) {
            float best = -1.0f;
#pragma unroll
            for (int m = 0; m < 32; m++) {
                // Bit-exact replication of the reference's fused d2.
                float dx = __fadd_rn(px[m], -qx);
                float dy = __fadd_rn(py[m], -qy);
                float dz = __fadd_rn(s_z[m * FPS_T + t], -qz);
                float d2 = __fmaf_rn(dz, dz, __fmaf_rn(dy, dy, __fmul_rn(dx, dx)));
                float mn = fminf(md[m], d2);
                md[m] = mn;
                best = fmaxf(best, mn);
            }
            lanebest = best;
            float s = __fsqrt_ru(lanebest) * 1.0005f + r;
            T = s * s;
        }

        // Selection: global max of lanebest (d2>=0 -> bit order == float order).
        unsigned lb_bits = __float_as_uint(lanebest);
        unsigned wm = __reduce_max_sync(0xFFFFFFFFu, lb_bits);
        if (lane == 0) s_wm[w] = wm;
        __syncthreads();                                 // BAR1
        unsigned v = __reduce_max_sync(0xFFFFFFFFu, s_wm[lane & 15]);
        int slot = it & 1;

        // Candidate threads: exact lowest-orig tie rule (atomicMax on ~orig).
        unsigned tinv = 0u; float tx = 0.0f, ty = 0.0f, tz = 0.0f;
        if (lb_bits == v) {
#pragma unroll
            for (int m = 0; m < 32; m++) {
                if (__float_as_uint(md[m]) == v) {
                    unsigned inv = ~(unsigned)s_or[m * FPS_T + t];
                    if (inv > tinv) {
                        tinv = inv;
                        tx = px[m]; ty = py[m]; tz = s_z[m * FPS_T + t];
                    }
                }
            }
            atomicMax(&s_win[slot], tinv);
        }
        __syncthreads();                                 // BAR2

        unsigned win = s_win[slot];
        if (tinv != 0u && tinv == win) {                 // unique winner thread
            s_q[0] = tx; s_q[1] = ty; s_q[2] = tz;
            g_idx[it] = (int)~win;
        }
        if (t == 0) s_win[slot ^ 1] = 0u;
        __syncthreads();                                 // BAR3
    }
}

// ---------------------------------------------------------------------------
// 2) Gather sampled positions (+ tuple tail if flattened output).
// ---------------------------------------------------------------------------
__global__ void gather_kernel(const float* __restrict__ pos, float* __restrict__ out, int out_size)
{
    int c = blockIdx.x * blockDim.x + threadIdx.x;
    if (c >= MC) return;
    int j = g_idx[c];
    float x = pos[3 * j + 0], y = pos[3 * j + 1], z = pos[3 * j + 2];
    g_pos_s[3 * c + 0] = x; g_pos_s[3 * c + 1] = y; g_pos_s[3 * c + 2] = z;
    int base = MC * FO;
    if (out_size >= base + 3 * MC) {
        out[base + 3 * c + 0] = x; out[base + 3 * c + 1] = y; out[base + 3 * c + 2] = z;
    }
    if (out_size >= base + 4 * MC) out[base + 3 * MC + c] = 0.0f;
}

// ---------------------------------------------------------------------------
// 3) Radius neighbors (unchanged, passing).
// ---------------------------------------------------------------------------
#define RB_C   16
#define RB_T   256
#define RB_CAP 192

__global__ __launch_bounds__(RB_T) void radius_kernel(const float* __restrict__ pos)
{
    __shared__ float scx[RB_C], scy[RB_C], scz[RB_C];
    __shared__ int   scnt[RB_C];
    __shared__ int   sidx[RB_C][RB_CAP];
    __shared__ float sd2[RB_C][RB_CAP];

    int t = threadIdx.x;
    int c0 = blockIdx.x * RB_C;
    if (t < RB_C) {
        scx[t] = g_pos_s[3 * (c0 + t) + 0];
        scy[t] = g_pos_s[3 * (c0 + t) + 1];
        scz[t] = g_pos_s[3 * (c0 + t) + 2];
        scnt[t] = 0;
    }
    __syncthreads();

    for (int j = t; j < NP; j += RB_T) {
        float x = pos[3 * j + 0], y = pos[3 * j + 1], z = pos[3 * j + 2];
#pragma unroll
        for (int c = 0; c < RB_C; c++) {
            float dx = __fadd_rn(scx[c], -x);
            float dy = __fadd_rn(scy[c], -y);
            float dz = __fadd_rn(scz[c], -z);
            float d2 = __fmaf_rn(dz, dz, __fmaf_rn(dy, dy, __fmul_rn(dx, dx)));
            if (d2 <= R2F) {
                int n = atomicAdd(&scnt[c], 1);
                if (n < RB_CAP) { sidx[c][n] = j; sd2[c][n] = d2; }
            }
        }
    }
    __syncthreads();

    for (int c = 0; c < RB_C; c++) {
        int cnt = min(scnt[c], RB_CAP);
        int cg = c0 + c;
        if (cnt <= KN) {
            if (t < cnt) g_nbr[cg * KN + t] = sidx[c][t];
            if (t == 0)  g_cnt[cg] = cnt;
        } else {
            for (int i = t; i < cnt; i += RB_T) {
                float di = sd2[c][i]; int ii = sidx[c][i];
                int rank = 0;
                for (int jj = 0; jj < cnt; jj++) {
                    float dj = sd2[c][jj];
                    rank += (dj < di) || (dj == di && sidx[c][jj] < ii);
                }
                if (rank < KN) g_nbr[cg * KN + rank] = ii;
            }
            if (t == 0) g_cnt[cg] = KN;
        }
    }
}

// ---------------------------------------------------------------------------
// 4) Per-edge MLP + max-pool (unchanged, passing).
// ---------------------------------------------------------------------------
#define ML_T    256
#define ML_GRID 304

#define OFF_W1 0
#define OFF_W2 (OFF_W1 + FD * FH)
#define OFF_W3 (OFF_W2 + FH * FH)
#define OFF_B1 (OFF_W3 + FH * FO)
#define OFF_B2 (OFF_B1 + FH)
#define OFF_B3 (OFF_B2 + FH)
#define OFF_F  (OFF_B3 + FO)
#define OFF_H  (OFF_F + KN * FPAD)
#define OFF_O  (OFF_H + KN * FPAD)
#define ML_SMEM ((OFF_O + FO) * 4)

__global__ __launch_bounds__(ML_T, 2) void mlp_kernel(
    const float* __restrict__ x, const float* __restrict__ pos,
    const float* __restrict__ W1, const float* __restrict__ b1,
    const float* __restrict__ W2, const float* __restrict__ b2,
    const float* __restrict__ W3, const float* __restrict__ b3,
    float* __restrict__ out)
{
    extern __shared__ float sm[];
    float* sW1 = sm + OFF_W1;
    float* sW2 = sm + OFF_W2;
    float* sW3 = sm + OFF_W3;
    float* sb1 = sm + OFF_B1;
    float* sb2 = sm + OFF_B2;
    float* sb3 = sm + OFF_B3;
    float* sF  = sm + OFF_F;
    float* sH  = sm + OFF_H;
    int*   sO  = (int*)(sm + OFF_O);

    int t = threadIdx.x;
    for (int i = t; i < FD * FH; i += ML_T) sW1[i] = W1[i];
    for (int i = t; i < FH * FH; i += ML_T) sW2[i] = W2[i];
    for (int i = t; i < FH * FO; i += ML_T) sW3[i] = W3[i];
    if (t < FH) { sb1[t] = b1[t]; sb2[t] = b2[t]; }
    if (t < FO) sb3[t] = b3[t];

    int ei = t >> 4, ci = t & 15;

    for (int c = blockIdx.x; c < MC; c += gridDim.x) {
        __syncthreads();
        if (t < FO) sO[t] = 0;
        int E = g_cnt[c];
        float cx = g_pos_s[3 * c + 0], cy = g_pos_s[3 * c + 1], cz = g_pos_s[3 * c + 2];

        {
            int e = t >> 2, q = t & 3;
            if (e < E) {
                int nb = g_nbr[c * KN + e];
                const float4* xr = (const float4*)(x + (size_t)nb * FIN);
                float4* dst = (float4*)(sF + e * FPAD + q * 16);
                dst[0] = xr[q * 4 + 0]; dst[1] = xr[q * 4 + 1];
                dst[2] = xr[q * 4 + 2]; dst[3] = xr[q * 4 + 3];
                if (q == 0) {
                    sF[e * FPAD + 64] = pos[3 * nb + 0] - cx;
                    sF[e * FPAD + 65] = pos[3 * nb + 1] - cy;
                    sF[e * FPAD + 66] = pos[3 * nb + 2] - cz;
                    sF[e * FPAD + 67] = 0.0f;
                }
            }
        }
        __syncthreads();
        int ET = (E + 3) >> 2;

        if (ei < ET) {
            float acc[4][4];
#pragma unroll
            for (int j = 0; j < 4; j++)
#pragma unroll
                for (int a = 0; a < 4; a++) acc[j][a] = sb1[ci * 4 + a];
#pragma unroll 4
            for (int k = 0; k < FD; k++) {
                float4 wv = *(const float4*)(sW1 + k * FH + ci * 4);
                float f[4];
#pragma unroll
                for (int j = 0; j < 4; j++) f[j] = sF[(4 * ei + j) * FPAD + k];
#pragma unroll
                for (int j = 0; j < 4; j++) {
                    acc[j][0] += f[j] * wv.x; acc[j][1] += f[j] * wv.y;
                    acc[j][2] += f[j] * wv.z; acc[j][3] += f[j] * wv.w;
                }
            }
#pragma unroll
            for (int j = 0; j < 4; j++)
#pragma unroll
                for (int a = 0; a < 4; a++)
                    sH[(4 * ei + j) * FPAD + ci * 4 + a] = fmaxf(acc[j][a], 0.0f);
        }
        __syncthreads();

        if (ei < ET) {
            float acc[4][4];
#pragma unroll
            for (int j = 0; j < 4; j++)
#pragma unroll
                for (int a = 0; a < 4; a++) acc[j][a] = sb2[ci * 4 + a];
#pragma unroll 4
            for (int k = 0; k < FH; k++) {
                float4 wv = *(const float4*)(sW2 + k * FH + ci * 4);
                float f[4];
#pragma unroll
                for (int j = 0; j < 4; j++) f[j] = sH[(4 * ei + j) * FPAD + k];
#pragma unroll
                for (int j = 0; j < 4; j++) {
                    acc[j][0] += f[j] * wv.x; acc[j][1] += f[j] * wv.y;
                    acc[j][2] += f[j] * wv.z; acc[j][3] += f[j] * wv.w;
                }
            }
#pragma unroll
            for (int j = 0; j < 4; j++)
#pragma unroll
                for (int a = 0; a < 4; a++)
                    sF[(4 * ei + j) * FPAD + ci * 4 + a] = fmaxf(acc[j][a], 0.0f);
        }
        __syncthreads();

        if (ei < ET) {
            float acc[4][8];
#pragma unroll
            for (int j = 0; j < 4; j++)
#pragma unroll
                for (int a = 0; a < 8; a++) acc[j][a] = sb3[ci * 8 + a];
#pragma unroll 4
            for (int k = 0; k < FH; k++) {
                float4 wa = *(const float4*)(sW3 + k * FO + ci * 8);
                float4 wb = *(const float4*)(sW3 + k * FO + ci * 8 + 4);
                float f[4];
#pragma unroll
                for (int j = 0; j < 4; j++) f[j] = sF[(4 * ei + j) * FPAD + k];
#pragma unroll
                for (int j = 0; j < 4; j++) {
                    acc[j][0] += f[j] * wa.x; acc[j][1] += f[j] * wa.y;
                    acc[j][2] += f[j] * wa.z; acc[j][3] += f[j] * wa.w;
                    acc[j][4] += f[j] * wb.x; acc[j][5] += f[j] * wb.y;
                    acc[j][6] += f[j] * wb.z; acc[j][7] += f[j] * wb.w;
                }
            }
#pragma unroll
            for (int a = 0; a < 8; a++) {
                float mv = -1.0f;
#pragma unroll
                for (int j = 0; j < 4; j++)
                    if (4 * ei + j < E) mv = fmaxf(mv, fmaxf(acc[j][a], 0.0f));
                if (mv >= 0.0f) atomicMax(&sO[ci * 8 + a], __float_as_int(mv));
            }
        }
        __syncthreads();
        if (t < FO) out[(size_t)c * FO + t] = __int_as_float(sO[t]);
    }
}

// ---------------------------------------------------------------------------
extern "C" void kernel_launch(void* const* d_in, const int* in_sizes, int n_in,
                              void* d_out, int out_size)
{
    const float* x   = (const float*)d_in[0];
    const float* pos = (const float*)d_in[1];
    const float* W1 = (const float*)d_in[3];
    const float* b1 = (const float*)d_in[4];
    const float* W2 = (const float*)d_in[5];
    const float* b2 = (const float*)d_in[6];
    const float* W3 = (const float*)d_in[7];
    const float* b3 = (const float*)d_in[8];
    float* out = (float*)d_out;

    cudaFuncSetAttribute(build_kernel, cudaFuncAttributeMaxDynamicSharedMemorySize, BLD_SMEM);
    cudaFuncSetAttribute(fps_kernel,   cudaFuncAttributeMaxDynamicSharedMemorySize, FPS_SMEM);
    cudaFuncSetAttribute(mlp_kernel,   cudaFuncAttributeMaxDynamicSharedMemorySize, ML_SMEM);

    build_kernel<<<1, BLD_T, BLD_SMEM>>>(pos);
    fps_kernel<<<1, FPS_T, FPS_SMEM>>>(pos);
    gather_kernel<<<(MC + 255) / 256, 256>>>(pos, out, out_size);
    radius_kernel<<<MC / RB_C, RB_T>>>(pos);
    mlp_kernel<<<ML_GRID, ML_T, ML_SMEM>>>(x, pos, W1, b1, W2, b2, W3, b3, out);
}

// round 10
// speedup vs baseline: 1.3765x; 1.0395x over previous
#include <cuda_runtime.h>
#include <cstdint>

typedef unsigned long long ull;

// Problem constants (fixed by the reference).
#define NP    16384
#define FIN   64
#define MC    4096
#define KN    64
#define FH    64
#define FO    128
#define FD    67
#define FPAD  68
#define R2F   0.04f

// Scratch (static __device__ — no allocations allowed).
__device__ int   g_idx[MC];
__device__ float g_pos_s[MC * 3];
__device__ int   g_nbr[MC * KN];
__device__ int   g_cnt[MC];
// Morton-reordered cloud
__device__ __align__(128) float g_px[NP];
__device__ __align__(128) float g_py[NP];
__device__ __align__(128) float g_pz[NP];
__device__ __align__(128) int   g_orig[NP];

// Packed f32x2 helpers (sm_103a): per-lane IEEE rn — bit-identical to scalar.
#define PACK2(out, lo, hi)  asm("mov.b64 %0, {%1, %2};" : "=l"(out) : "f"(lo), "f"(hi))
#define UNPACK2(lo, hi, in) asm("mov.b64 {%0, %1}, %2;" : "=f"(lo), "=f"(hi) : "l"(in))
#define ADD2(out, a, b)     asm("add.rn.f32x2 %0, %1, %2;" : "=l"(out) : "l"(a), "l"(b))
#define MUL2(out, a, b)     asm("mul.rn.f32x2 %0, %1, %2;" : "=l"(out) : "l"(a), "l"(b))
#define FMA2(out, a, b, c)  asm("fma.rn.f32x2 %0, %1, %2, %3;" : "=l"(out) : "l"(a), "l"(b), "l"(c))

// ---------------------------------------------------------------------------
// 0) Build: Morton sort (bitonic, one CTA) -> reordered coords.
// ---------------------------------------------------------------------------
__device__ __forceinline__ unsigned expand10(unsigned v) {
    v &= 1023u;
    v = (v | (v << 16)) & 0x030000FFu;
    v = (v | (v << 8))  & 0x0300F00Fu;
    v = (v | (v << 4))  & 0x030C30C3u;
    v = (v | (v << 2))  & 0x09249249u;
    return v;
}

#define BLD_T 512
#define BLD_SMEM (NP * 8)

__global__ __launch_bounds__(BLD_T) void build_kernel(const float* __restrict__ pos)
{
    extern __shared__ ull sk[];
    int t = threadIdx.x;

    for (int i = t; i < NP; i += BLD_T) {
        float x = pos[3 * i + 0], y = pos[3 * i + 1], z = pos[3 * i + 2];
        unsigned ux = (unsigned)fminf(1023.f, fmaxf(0.f, (x + 5.12f) * 100.0f));
        unsigned uy = (unsigned)fminf(1023.f, fmaxf(0.f, (y + 5.12f) * 100.0f));
        unsigned uz = (unsigned)fminf(1023.f, fmaxf(0.f, (z + 5.12f) * 100.0f));
        unsigned code = (expand10(ux) << 2) | (expand10(uy) << 1) | expand10(uz);
        sk[i] = ((ull)code << 32) | (unsigned)i;
    }
    __syncthreads();

    for (unsigned k2 = 2; k2 <= NP; k2 <<= 1) {
        for (unsigned j = k2 >> 1; j > 0; j >>= 1) {
            for (unsigned i = t; i < NP; i += BLD_T) {
                unsigned ixj = i ^ j;
                if (ixj > i) {
                    ull a = sk[i], b = sk[ixj];
                    bool up = ((i & k2) == 0);
                    if ((a > b) == up) { sk[i] = b; sk[ixj] = a; }
                }
            }
            __syncthreads();
        }
    }

    for (int i = t; i < NP; i += BLD_T) {
        unsigned idx = (unsigned)sk[i];
        g_px[i] = pos[3 * idx + 0];
        g_py[i] = pos[3 * idx + 1];
        g_pz[i] = pos[3 * idx + 2];
        g_orig[i] = (int)idx;
    }
}

// ---------------------------------------------------------------------------
// 1) FPS — single persistent CTA, 512 threads. Thread t owns the 32
//    Morton-contiguous points [32t, 32t+32).
//    Update loop uses packed f32x2 math (bit-identical to scalar rn ops):
//      x pairs in registers (px2[16]), y/z pairs in smem (one LDS.64 each),
//      md[32] in registers with STATIC indexing only.
//    Per-thread bounding-sphere prune (value-preserving -> bit-identical).
//    orig indices in smem as u16 (only touched by the rare candidate path).
// ---------------------------------------------------------------------------
#define FPS_T 512
#define OY2   0
#define OZ2   (OY2 + (NP / 2) * 8)
#define OOR   (OZ2 + (NP / 2) * 8)
#define OMISC (OOR + NP * 2)
#define FPS_SMEM (OMISC + 128)

__global__ __launch_bounds__(FPS_T) void fps_kernel(const float* __restrict__ pos)
{
    extern __shared__ unsigned char raw[];
    float2*         s_y2  = (float2*)(raw + OY2);          // [NP/2] pair layout
    float2*         s_z2  = (float2*)(raw + OZ2);          // [NP/2] pair layout
    unsigned short* s_or  = (unsigned short*)(raw + OOR);  // [NP] transposed
    unsigned*       s_wm  = (unsigned*)(raw + OMISC);      // [16]
    unsigned*       s_win = s_wm + 16;                     // [2]
    float*          s_q   = (float*)(s_win + 2);           // [3]

    const int t = threadIdx.x, lane = t & 31, w = t >> 5;
    const int base = t * 32;
    const float INF = __int_as_float(0x7f800000);

    ull   px2[16];
    float md[32];
    float xlo = 1e30f, xhi = -1e30f, ylo = 1e30f, yhi = -1e30f, zlo = 1e30f, zhi = -1e30f;
#pragma unroll
    for (int i = 0; i < 16; i++) {
        int p = base + 2 * i;
        float x0 = g_px[p], x1 = g_px[p + 1];
        float y0 = g_py[p], y1 = g_py[p + 1];
        float z0 = g_pz[p], z1 = g_pz[p + 1];
        PACK2(px2[i], x0, x1);
        s_y2[i * FPS_T + t] = make_float2(y0, y1);
        s_z2[i * FPS_T + t] = make_float2(z0, z1);
        s_or[(2 * i) * FPS_T + t]     = (unsigned short)g_orig[p];
        s_or[(2 * i + 1) * FPS_T + t] = (unsigned short)g_orig[p + 1];
        md[2 * i] = INF; md[2 * i + 1] = INF;
        xlo = fminf(xlo, fminf(x0, x1)); xhi = fmaxf(xhi, fmaxf(x0, x1));
        ylo = fminf(ylo, fminf(y0, y1)); yhi = fmaxf(yhi, fmaxf(y0, y1));
        zlo = fminf(zlo, fminf(z0, z1)); zhi = fmaxf(zhi, fmaxf(z0, z1));
    }
    float cx = 0.5f * (xlo + xhi), cy = 0.5f * (ylo + yhi), cz = 0.5f * (zlo + zhi);
    float r2m = 0.0f;
#pragma unroll
    for (int i = 0; i < 16; i++) {
        float x0, x1; UNPACK2(x0, x1, px2[i]);
        float2 y2 = s_y2[i * FPS_T + t];
        float2 z2 = s_z2[i * FPS_T + t];
        float dx = x0 - cx, dy = y2.x - cy, dz = z2.x - cz;
        r2m = fmaxf(r2m, dx * dx + dy * dy + dz * dz);
        dx = x1 - cx; dy = y2.y - cy; dz = z2.y - cz;
        r2m = fmaxf(r2m, dx * dx + dy * dy + dz * dz);
    }
    float rad = __fsqrt_ru(r2m) * 1.0005f + 1e-4f;
    float lanebest = INF;

    if (t == 0) {
        g_idx[0] = 0;
        s_q[0] = pos[0]; s_q[1] = pos[1]; s_q[2] = pos[2];
        s_win[0] = 0u; s_win[1] = 0u;
    }
    __syncthreads();

    for (int it = 1; it < MC; it++) {
        float qx = s_q[0], qy = s_q[1], qz = s_q[2];

        // Sphere prune: skip iff q provably can't lower any md in this thread.
        float ddx = qx - cx, ddy = qy - cy, ddz = qz - cz;
        float d2c = ddx * ddx + ddy * ddy + ddz * ddz;
        float thr = __fsqrt_ru(lanebest) * 1.0005f + rad;   // INF stays INF
        if (d2c < thr * thr) {
            ull qx2, qy2, qz2;
            float nqx = -qx, nqy = -qy, nqz = -qz;
            PACK2(qx2, nqx, nqx); PACK2(qy2, nqy, nqy); PACK2(qz2, nqz, nqz);
            float best = -1.0f;
#pragma unroll
            for (int i = 0; i < 16; i++) {
                float2 y2 = s_y2[i * FPS_T + t];
                float2 z2 = s_z2[i * FPS_T + t];
                ull py2, pz2, dx2, dy2, dz2, s1, s2, d2p;
                PACK2(py2, y2.x, y2.y);
                PACK2(pz2, z2.x, z2.y);
                ADD2(dx2, px2[i], qx2);            // x - qx (rn, per lane)
                ADD2(dy2, py2, qy2);
                ADD2(dz2, pz2, qz2);
                MUL2(s1, dx2, dx2);                // dx*dx
                FMA2(s2, dy2, dy2, s1);            // fma(dy,dy,·)
                FMA2(d2p, dz2, dz2, s2);           // fma(dz,dz,·)
                float d2a, d2b; UNPACK2(d2a, d2b, d2p);
                float m0 = fminf(md[2 * i], d2a);
                float m1 = fminf(md[2 * i + 1], d2b);
                md[2 * i] = m0; md[2 * i + 1] = m1;
                best = fmaxf(best, fmaxf(m0, m1));
            }
            lanebest = best;
        }

        // Selection: global max of lanebest (d2>=0 -> bit order == float order).
        unsigned lb = __float_as_uint(lanebest);
        unsigned wm = __reduce_max_sync(0xFFFFFFFFu, lb);
        if (lane == 0) s_wm[w] = wm;
        __syncthreads();                                  // BAR1
        unsigned v = __reduce_max_sync(0xFFFFFFFFu, s_wm[lane & 15]);
        int slot = it & 1;

        // Candidate threads: exact lowest-orig tie rule (atomicMax on ~orig).
        unsigned tinv = 0u; float tx = 0.0f, ty = 0.0f, tz = 0.0f;
        if (lb == v) {
#pragma unroll
            for (int m = 0; m < 32; m++) {
                if (__float_as_uint(md[m]) == v) {
                    unsigned inv = 0xFFFFFFFFu - (unsigned)s_or[m * FPS_T + t];
                    if (inv > tinv) {
                        tinv = inv;
                        float a, b; UNPACK2(a, b, px2[m >> 1]);
                        tx = (m & 1) ? b : a;
                        float2 y2 = s_y2[(m >> 1) * FPS_T + t];
                        float2 z2 = s_z2[(m >> 1) * FPS_T + t];
                        ty = (m & 1) ? y2.y : y2.x;
                        tz = (m & 1) ? z2.y : z2.x;
                    }
                }
            }
            atomicMax(&s_win[slot], tinv);
        }
        if (t == 0) s_win[slot ^ 1] = 0u;
        __syncthreads();                                  // BAR2

        unsigned win = s_win[slot];
        if (tinv != 0u && tinv == win) {                  // unique winner thread
            s_q[0] = tx; s_q[1] = ty; s_q[2] = tz;
            g_idx[it] = (int)(0xFFFFFFFFu - win);
        }
        __syncthreads();                                  // BAR3
    }
}

// ---------------------------------------------------------------------------
// 2) Gather sampled positions (+ tuple tail if flattened output).
// ---------------------------------------------------------------------------
__global__ void gather_kernel(const float* __restrict__ pos, float* __restrict__ out, int out_size)
{
    int c = blockIdx.x * blockDim.x + threadIdx.x;
    if (c >= MC) return;
    int j = g_idx[c];
    float x = pos[3 * j + 0], y = pos[3 * j + 1], z = pos[3 * j + 2];
    g_pos_s[3 * c + 0] = x; g_pos_s[3 * c + 1] = y; g_pos_s[3 * c + 2] = z;
    int base = MC * FO;
    if (out_size >= base + 3 * MC) {
        out[base + 3 * c + 0] = x; out[base + 3 * c + 1] = y; out[base + 3 * c + 2] = z;
    }
    if (out_size >= base + 4 * MC) out[base + 3 * MC + c] = 0.0f;
}

// ---------------------------------------------------------------------------
// 3) Radius neighbors (unchanged, passing).
// ---------------------------------------------------------------------------
#define RB_C   16
#define RB_T   256
#define RB_CAP 192

__global__ __launch_bounds__(RB_T) void radius_kernel(const float* __restrict__ pos)
{
    __shared__ float scx[RB_C], scy[RB_C], scz[RB_C];
    __shared__ int   scnt[RB_C];
    __shared__ int   sidx[RB_C][RB_CAP];
    __shared__ float sd2[RB_C][RB_CAP];

    int t = threadIdx.x;
    int c0 = blockIdx.x * RB_C;
    if (t < RB_C) {
        scx[t] = g_pos_s[3 * (c0 + t) + 0];
        scy[t] = g_pos_s[3 * (c0 + t) + 1];
        scz[t] = g_pos_s[3 * (c0 + t) + 2];
        scnt[t] = 0;
    }
    __syncthreads();

    for (int j = t; j < NP; j += RB_T) {
        float x = pos[3 * j + 0], y = pos[3 * j + 1], z = pos[3 * j + 2];
#pragma unroll
        for (int c = 0; c < RB_C; c++) {
            float dx = __fadd_rn(scx[c], -x);
            float dy = __fadd_rn(scy[c], -y);
            float dz = __fadd_rn(scz[c], -z);
            float d2 = __fmaf_rn(dz, dz, __fmaf_rn(dy, dy, __fmul_rn(dx, dx)));
            if (d2 <= R2F) {
                int n = atomicAdd(&scnt[c], 1);
                if (n < RB_CAP) { sidx[c][n] = j; sd2[c][n] = d2; }
            }
        }
    }
    __syncthreads();

    for (int c = 0; c < RB_C; c++) {
        int cnt = min(scnt[c], RB_CAP);
        int cg = c0 + c;
        if (cnt <= KN) {
            if (t < cnt) g_nbr[cg * KN + t] = sidx[c][t];
            if (t == 0)  g_cnt[cg] = cnt;
        } else {
            for (int i = t; i < cnt; i += RB_T) {
                float di = sd2[c][i]; int ii = sidx[c][i];
                int rank = 0;
                for (int jj = 0; jj < cnt; jj++) {
                    float dj = sd2[c][jj];
                    rank += (dj < di) || (dj == di && sidx[c][jj] < ii);
                }
                if (rank < KN) g_nbr[cg * KN + rank] = ii;
            }
            if (t == 0) g_cnt[cg] = KN;
        }
    }
}

// ---------------------------------------------------------------------------
// 4) Per-edge MLP + max-pool (unchanged, passing).
// ---------------------------------------------------------------------------
#define ML_T    256
#define ML_GRID 304

#define OFF_W1 0
#define OFF_W2 (OFF_W1 + FD * FH)
#define OFF_W3 (OFF_W2 + FH * FH)
#define OFF_B1 (OFF_W3 + FH * FO)
#define OFF_B2 (OFF_B1 + FH)
#define OFF_B3 (OFF_B2 + FH)
#define OFF_F  (OFF_B3 + FO)
#define OFF_H  (OFF_F + KN * FPAD)
#define OFF_O  (OFF_H + KN * FPAD)
#define ML_SMEM ((OFF_O + FO) * 4)

__global__ __launch_bounds__(ML_T, 2) void mlp_kernel(
    const float* __restrict__ x, const float* __restrict__ pos,
    const float* __restrict__ W1, const float* __restrict__ b1,
    const float* __restrict__ W2, const float* __restrict__ b2,
    const float* __restrict__ W3, const float* __restrict__ b3,
    float* __restrict__ out)
{
    extern __shared__ float sm[];
    float* sW1 = sm + OFF_W1;
    float* sW2 = sm + OFF_W2;
    float* sW3 = sm + OFF_W3;
    float* sb1 = sm + OFF_B1;
    float* sb2 = sm + OFF_B2;
    float* sb3 = sm + OFF_B3;
    float* sF  = sm + OFF_F;
    float* sH  = sm + OFF_H;
    int*   sO  = (int*)(sm + OFF_O);

    int t = threadIdx.x;
    for (int i = t; i < FD * FH; i += ML_T) sW1[i] = W1[i];
    for (int i = t; i < FH * FH; i += ML_T) sW2[i] = W2[i];
    for (int i = t; i < FH * FO; i += ML_T) sW3[i] = W3[i];
    if (t < FH) { sb1[t] = b1[t]; sb2[t] = b2[t]; }
    if (t < FO) sb3[t] = b3[t];

    int ei = t >> 4, ci = t & 15;

    for (int c = blockIdx.x; c < MC; c += gridDim.x) {
        __syncthreads();
        if (t < FO) sO[t] = 0;
        int E = g_cnt[c];
        float cx = g_pos_s[3 * c + 0], cy = g_pos_s[3 * c + 1], cz = g_pos_s[3 * c + 2];

        {
            int e = t >> 2, q = t & 3;
            if (e < E) {
                int nb = g_nbr[c * KN + e];
                const float4* xr = (const float4*)(x + (size_t)nb * FIN);
                float4* dst = (float4*)(sF + e * FPAD + q * 16);
                dst[0] = xr[q * 4 + 0]; dst[1] = xr[q * 4 + 1];
                dst[2] = xr[q * 4 + 2]; dst[3] = xr[q * 4 + 3];
                if (q == 0) {
                    sF[e * FPAD + 64] = pos[3 * nb + 0] - cx;
                    sF[e * FPAD + 65] = pos[3 * nb + 1] - cy;
                    sF[e * FPAD + 66] = pos[3 * nb + 2] - cz;
                    sF[e * FPAD + 67] = 0.0f;
                }
            }
        }
        __syncthreads();
        int ET = (E + 3) >> 2;

        if (ei < ET) {
            float acc[4][4];
#pragma unroll
            for (int j = 0; j < 4; j++)
#pragma unroll
                for (int a = 0; a < 4; a++) acc[j][a] = sb1[ci * 4 + a];
#pragma unroll 4
            for (int k = 0; k < FD; k++) {
                float4 wv = *(const float4*)(sW1 + k * FH + ci * 4);
                float f[4];
#pragma unroll
                for (int j = 0; j < 4; j++) f[j] = sF[(4 * ei + j) * FPAD + k];
#pragma unroll
                for (int j = 0; j < 4; j++) {
                    acc[j][0] += f[j] * wv.x; acc[j][1] += f[j] * wv.y;
                    acc[j][2] += f[j] * wv.z; acc[j][3] += f[j] * wv.w;
                }
            }
#pragma unroll
            for (int j = 0; j < 4; j++)
#pragma unroll
                for (int a = 0; a < 4; a++)
                    sH[(4 * ei + j) * FPAD + ci * 4 + a] = fmaxf(acc[j][a], 0.0f);
        }
        __syncthreads();

        if (ei < ET) {
            float acc[4][4];
#pragma unroll
            for (int j = 0; j < 4; j++)
#pragma unroll
                for (int a = 0; a < 4; a++) acc[j][a] = sb2[ci * 4 + a];
#pragma unroll 4
            for (int k = 0; k < FH; k++) {
                float4 wv = *(const float4*)(sW2 + k * FH + ci * 4);
                float f[4];
#pragma unroll
                for (int j = 0; j < 4; j++) f[j] = sH[(4 * ei + j) * FPAD + k];
#pragma unroll
                for (int j = 0; j < 4; j++) {
                    acc[j][0] += f[j] * wv.x; acc[j][1] += f[j] * wv.y;
                    acc[j][2] += f[j] * wv.z; acc[j][3] += f[j] * wv.w;
                }
            }
#pragma unroll
            for (int j = 0; j < 4; j++)
#pragma unroll
                for (int a = 0; a < 4; a++)
                    sF[(4 * ei + j) * FPAD + ci * 4 + a] = fmaxf(acc[j][a], 0.0f);
        }
        __syncthreads();

        if (ei < ET) {
            float acc[4][8];
#pragma unroll
            for (int j = 0; j < 4; j++)
#pragma unroll
                for (int a = 0; a < 8; a++) acc[j][a] = sb3[ci * 8 + a];
#pragma unroll 4
            for (int k = 0; k < FH; k++) {
                float4 wa = *(const float4*)(sW3 + k * FO + ci * 8);
                float4 wb = *(const float4*)(sW3 + k * FO + ci * 8 + 4);
                float f[4];
#pragma unroll
                for (int j = 0; j < 4; j++) f[j] = sF[(4 * ei + j) * FPAD + k];
#pragma unroll
                for (int j = 0; j < 4; j++) {
                    acc[j][0] += f[j] * wa.x; acc[j][1] += f[j] * wa.y;
                    acc[j][2] += f[j] * wa.z; acc[j][3] += f[j] * wa.w;
                    acc[j][4] += f[j] * wb.x; acc[j][5] += f[j] * wb.y;
                    acc[j][6] += f[j] * wb.z; acc[j][7] += f[j] * wb.w;
                }
            }
#pragma unroll
            for (int a = 0; a < 8; a++) {
                float mv = -1.0f;
#pragma unroll
                for (int j = 0; j < 4; j++)
                    if (4 * ei + j < E) mv = fmaxf(mv, fmaxf(acc[j][a], 0.0f));
                if (mv >= 0.0f) atomicMax(&sO[ci * 8 + a], __float_as_int(mv));
            }
        }
        __syncthreads();
        if (t < FO) out[(size_t)c * FO + t] = __int_as_float(sO[t]);
    }
}

// ---------------------------------------------------------------------------
extern "C" void kernel_launch(void* const* d_in, const int* in_sizes, int n_in,
                              void* d_out, int out_size)
{
    const float* x   = (const float*)d_in[0];
    const float* pos = (const float*)d_in[1];
    const float* W1 = (const float*)d_in[3];
    const float* b1 = (const float*)d_in[4];
    const float* W2 = (const float*)d_in[5];
    const float* b2 = (const float*)d_in[6];
    const float* W3 = (const float*)d_in[7];
    const float* b3 = (const float*)d_in[8];
    float* out = (float*)d_out;

    cudaFuncSetAttribute(build_kernel, cudaFuncAttributeMaxDynamicSharedMemorySize, BLD_SMEM);
    cudaFuncSetAttribute(fps_kernel,   cudaFuncAttributeMaxDynamicSharedMemorySize, FPS_SMEM);
    cudaFuncSetAttribute(mlp_kernel,   cudaFuncAttributeMaxDynamicSharedMemorySize, ML_SMEM);

    build_kernel<<<1, BLD_T, BLD_SMEM>>>(pos);
    fps_kernel<<<1, FPS_T, FPS_SMEM>>>(pos);
    gather_kernel<<<(MC + 255) / 256, 256>>>(pos, out, out_size);
    radius_kernel<<<MC / RB_C, RB_T>>>(pos);
    mlp_kernel<<<ML_GRID, ML_T, ML_SMEM>>>(x, pos, W1, b1, W2, b2, W3, b3, out);
}